// round 5
// baseline (speedup 1.0000x reference)
#include <cuda_runtime.h>
#include <math.h>

#define Bc   4
#define Cc   64
#define NH   4
#define Dh   16
#define Hc   256
#define Wc   256
#define HWc  (Hc*Wc)
#define HWHc (HWc/2)

// ---------------- scratch (device globals; no allocation allowed) ----------------
__device__ float g_qpre[Bc*Cc*HWc];
__device__ float g_kpre[Bc*Cc*HWc];
__device__ float g_vpre[Bc*Cc*HWc];
__device__ float g_qs  [Bc*Cc*HWHc];
__device__ float g_ks  [Bc*Cc*HWHc];
__device__ float g_vs  [Bc*Cc*HWHc];
__device__ float g_ctx [Bc*NH*Dh*Dh];
__device__ float g_att [Bc*Cc*HWc];
__device__ float g_attn[Bc*2*Cc*HWc];
__device__ float g_ma  [Bc*4*Cc*HWc];
__device__ float g_mb  [Bc*4*Cc*HWc];

__device__ __forceinline__ float gelu_exact(float x) {
    return 0.5f * x * (1.0f + erff(x * 0.70710678118654752f));
}

// ---------------- generic 1x1 conv (GEMM) ----------------
// out[b,oc,n] = act( sum_ic W[oc,ic] * mask(in[b,ic,n]) + bias[oc] ) (+ res)
// MASK: 0 none, 1 keep (i+j)%2==1 (anchor), 2 keep (i+j)%2==0 (nonanchor)
// grid: (HW/64, OC/64, B), block 256.  each thread: 4 oc x 4 px.
template<int MASK, int ACT, int RES>
__global__ void conv1x1_kernel(const float* __restrict__ in, const float* __restrict__ w,
                               const float* __restrict__ bias, const float* __restrict__ res,
                               float* __restrict__ out, int IC, int OC)
{
    __shared__ __align__(16) float xs [16][64];
    __shared__ __align__(16) float wsm[16][68];
    const int b   = blockIdx.z;
    const int n0  = blockIdx.x * 64;
    const int oc0 = blockIdx.y * 64;
    const int tid = threadIdx.x;
    const int tpx = tid & 15;
    const int toc = tid >> 4;
    const int i   = n0 >> 8;      // W = 256
    const int j0  = n0 & 255;

    float acc[4][4];
#pragma unroll
    for (int o = 0; o < 4; o++)
#pragma unroll
        for (int p = 0; p < 4; p++) acc[o][p] = 0.f;

    const float* inb = in + (size_t)b * IC * HWc + n0;

    for (int ic0 = 0; ic0 < IC; ic0 += 16) {
#pragma unroll
        for (int l = 0; l < 4; l++) {
            int idx = tid + l * 256;
            int kk = idx >> 6, px = idx & 63;
            float v = inb[(size_t)(ic0 + kk) * HWc + px];
            if (MASK) {
                int par = (i + j0 + px) & 1;
                if (MASK == 1 && par == 0) v = 0.f;
                if (MASK == 2 && par == 1) v = 0.f;
            }
            xs[kk][px] = v;
        }
#pragma unroll
        for (int l = 0; l < 4; l++) {
            int idx = tid + l * 256;
            int kk = idx & 15, oc = idx >> 4;
            wsm[kk][oc] = w[(size_t)(oc0 + oc) * IC + ic0 + kk];
        }
        __syncthreads();
#pragma unroll
        for (int kk = 0; kk < 16; kk++) {
            float4 xv4 = *(const float4*)(&xs[kk][tpx << 2]);
            float4 wv4 = *(const float4*)(&wsm[kk][toc << 2]);
            float xv[4] = {xv4.x, xv4.y, xv4.z, xv4.w};
            float wv[4] = {wv4.x, wv4.y, wv4.z, wv4.w};
#pragma unroll
            for (int o = 0; o < 4; o++)
#pragma unroll
                for (int p = 0; p < 4; p++) acc[o][p] += wv[o] * xv[p];
        }
        __syncthreads();
    }

#pragma unroll
    for (int o = 0; o < 4; o++) {
        int oc = oc0 + (toc << 2) + o;
        float bs = bias[oc];
        size_t obase = ((size_t)b * OC + oc) * HWc + n0 + (tpx << 2);
#pragma unroll
        for (int p = 0; p < 4; p++) {
            float v = acc[o][p] + bs;
            if (ACT) v = gelu_exact(v);
            if (RES) v += res[obase + p];
            out[obase + p] = v;
        }
    }
}

// ---------------- depthwise 3x3 + checkerboard squeeze ----------------
// flag=0: col=2j+(i&1) (nonanchor squeeze); flag=1: col=2j+((i+1)&1) (anchor)
__global__ void dw3x3_squeeze_kernel(const float* __restrict__ in, const float* __restrict__ w,
                                     const float* __restrict__ bias, float* __restrict__ out, int flag)
{
    int idx = blockIdx.x * 256 + threadIdx.x;          // Bc*Cc*Hc*(Wc/2)
    int j2 = idx & 127;
    int i  = (idx >> 7) & 255;
    int c  = (idx >> 15) & 63;
    int b  = idx >> 21;
    int col = 2 * j2 + ((i + flag) & 1);
    const float* wp = w + c * 9;
    const float* ip = in + (size_t)(b * Cc + c) * HWc;
    float s = bias[c];
#pragma unroll
    for (int ky = 0; ky < 3; ky++) {
        int ii = i + ky - 1;
        if (ii < 0 || ii >= Hc) continue;
#pragma unroll
        for (int kx = 0; kx < 3; kx++) {
            int jj = col + kx - 1;
            if (jj < 0 || jj >= Wc) continue;
            s += wp[ky * 3 + kx] * ip[ii * Wc + jj];
        }
    }
    out[idx] = s;
}

// ---------------- softmax over contiguous rows (k: per (b,c) over 32768) ----------------
__global__ void softmax_rows_kernel(float* __restrict__ data, int len)
{
    __shared__ float red[256];
    float* row = data + (size_t)blockIdx.x * len;
    int tid = threadIdx.x;
    float m = -1e30f;
    for (int n = tid; n < len; n += 256) m = fmaxf(m, row[n]);
    red[tid] = m; __syncthreads();
    for (int s = 128; s > 0; s >>= 1) { if (tid < s) red[tid] = fmaxf(red[tid], red[tid + s]); __syncthreads(); }
    m = red[0]; __syncthreads();
    float sum = 0.f;
    for (int n = tid; n < len; n += 256) sum += expf(row[n] - m);
    red[tid] = sum; __syncthreads();
    for (int s = 128; s > 0; s >>= 1) { if (tid < s) red[tid] += red[tid + s]; __syncthreads(); }
    float inv = 1.0f / red[0];
    for (int n = tid; n < len; n += 256) row[n] = expf(row[n] - m) * inv;
}

// ---------------- softmax over d (16 channels within head) for q ----------------
__global__ void softmax_d_kernel(float* __restrict__ q)
{
    int idx = blockIdx.x * 256 + threadIdx.x;          // Bc*NH*HWHc
    int pos = idx & (HWHc - 1);
    int bh  = idx >> 15;
    float* base = q + (size_t)bh * Dh * HWHc + pos;
    float v[16]; float m = -1e30f;
#pragma unroll
    for (int d = 0; d < 16; d++) { v[d] = base[(size_t)d * HWHc]; m = fmaxf(m, v[d]); }
    float s = 0.f;
#pragma unroll
    for (int d = 0; d < 16; d++) { v[d] = expf(v[d] - m); s += v[d]; }
    float inv = 1.0f / s;
#pragma unroll
    for (int d = 0; d < 16; d++) base[(size_t)d * HWHc] = v[d] * inv;
}

// ---------------- ctx[d][e] = sum_n k_soft[d,n] * v[e,n]  (per b,head) ----------------
__global__ void ctx_kernel(const float* __restrict__ ks, const float* __restrict__ vs,
                           float* __restrict__ ctx)
{
    __shared__ __align__(16) float sk[16][260];
    __shared__ __align__(16) float sv[16][260];
    int bh = blockIdx.x, tid = threadIdx.x;
    int d = tid >> 4, e = tid & 15;
    const float* kb = ks + (size_t)bh * Dh * HWHc;
    const float* vb = vs + (size_t)bh * Dh * HWHc;
    float acc = 0.f;
    for (int n0 = 0; n0 < HWHc; n0 += 256) {
#pragma unroll
        for (int l = 0; l < 16; l++) {
            int idx = tid + l * 256;
            int dd = idx >> 8, nn = idx & 255;
            sk[dd][nn] = kb[(size_t)dd * HWHc + n0 + nn];
            sv[dd][nn] = vb[(size_t)dd * HWHc + n0 + nn];
        }
        __syncthreads();
#pragma unroll 4
        for (int nn = 0; nn < 256; nn += 4) {
            float4 a  = *(const float4*)&sk[d][nn];
            float4 bq = *(const float4*)&sv[e][nn];
            acc += a.x * bq.x + a.y * bq.y + a.z * bq.z + a.w * bq.w;
        }
        __syncthreads();
    }
    ctx[bh * 256 + tid] = acc;
}

// ---------------- att[e,n] at nonanchor = sum_d ctx[d][e]*q[d,n]; zeros at anchor ---------
__global__ void att_kernel(const float* __restrict__ q, const float* __restrict__ ctx,
                           float* __restrict__ att)
{
    __shared__ float sctx[256];
    int bh = blockIdx.z;
    int tid = threadIdx.x;
    sctx[tid] = ctx[bh * 256 + tid];
    __syncthreads();
    int pos = blockIdx.x * 256 + tid;
    int i = pos >> 7, j2 = pos & 127;
    const float* qb = q + (size_t)bh * Dh * HWHc + pos;
    float qv[16];
#pragma unroll
    for (int d = 0; d < 16; d++) qv[d] = qb[(size_t)d * HWHc];
    int b = bh >> 2, hd = bh & 3;
    int col = 2 * j2 + (i & 1);
#pragma unroll
    for (int e = 0; e < 16; e++) {
        float s = 0.f;
#pragma unroll
        for (int d = 0; d < 16; d++) s += sctx[d * 16 + e] * qv[d];
        size_t o = ((size_t)(b * Cc + hd * Dh + e) * Hc + i) * Wc;
        att[o + col]       = s;
        att[o + (col ^ 1)] = 0.f;
    }
}

// ---------------- 5x5 conv 64->128, pad 2, input zero at anchor positions ----------------
// grid (Wc/32, Hc, Bc), block 256.  Parity-split: warps 0-3 even-parity px, 4-7 odd.
#define TAP5(kx) { \
    float w0 = __ldg(wb + (kx));        float w1 = __ldg(wb + 1600 + (kx)); \
    float w2 = __ldg(wb + 3200 + (kx)); float w3 = __ldg(wb + 4800 + (kx)); \
    float xa = rowp[(kx)]; float xb = rowp[(kx)+2]; float xc = rowp[(kx)+4]; float xd = rowp[(kx)+6]; \
    acc[0][0] += w0*xa; acc[0][1] += w0*xb; acc[0][2] += w0*xc; acc[0][3] += w0*xd; \
    acc[1][0] += w1*xa; acc[1][1] += w1*xb; acc[1][2] += w1*xc; acc[1][3] += w1*xd; \
    acc[2][0] += w2*xa; acc[2][1] += w2*xb; acc[2][2] += w2*xc; acc[2][3] += w2*xd; \
    acc[3][0] += w3*xa; acc[3][1] += w3*xb; acc[3][2] += w3*xc; acc[3][3] += w3*xd; }

__global__ void conv5x5_kernel(const float* __restrict__ in, const float* __restrict__ w,
                               const float* __restrict__ bias, float* __restrict__ out)
{
    __shared__ float s_in[64][5][36];
    const int b  = blockIdx.z;
    const int i  = blockIdx.y;
    const int j0 = blockIdx.x * 32;
    const int tid = threadIdx.x;

    for (int lin = tid; lin < 64 * 5 * 36; lin += 256) {
        int ic = lin / 180;
        int r  = (lin % 180) / 36;
        int cc = lin % 36;
        int ii = i + r - 2;
        int jj = j0 + cc - 2;
        float v = 0.f;
        if (ii >= 0 && ii < Hc && jj >= 0 && jj < Wc)
            v = in[((size_t)(b * Cc + ic) * Hc + ii) * Wc + jj];
        s_in[ic][r][cc] = v;
    }
    __syncthreads();

    const int par = tid >> 7;                 // warp-uniform parity (warps 0-3:0, 4-7:1)
    const int t2  = tid & 127;
    const int toc = t2 >> 2;                  // 0..31
    const int pg  = t2 & 3;                   // 0..3
    const int jbase = pg * 8 + par;           // output cols jbase + 2p
    const int oc = toc * 4;

    float acc[4][4];
#pragma unroll
    for (int o = 0; o < 4; o++)
#pragma unroll
        for (int p = 0; p < 4; p++) acc[o][p] = 0.f;

    const float* wbase = w + (size_t)oc * 1600;   // 64*25
    for (int ic = 0; ic < 64; ic++) {
#pragma unroll
        for (int ky = 0; ky < 5; ky++) {
            const float* rowp = &s_in[ic][ky][jbase];
            const float* wb = wbase + ic * 25 + ky * 5;
            int kxs = (i + ky + par) & 1;     // warp-uniform
            if (kxs == 0) { TAP5(0); TAP5(2); TAP5(4); }
            else          { TAP5(1); TAP5(3); }
        }
    }

#pragma unroll
    for (int o = 0; o < 4; o++) {
        float bs = bias[oc + o];
        size_t ob = ((size_t)(b * 128 + oc + o) * Hc + i) * Wc + j0 + jbase;
#pragma unroll
        for (int p = 0; p < 4; p++) out[ob + 2 * p] = acc[o][p] + bs;
    }
}

// ---------------- depthwise 3x3 (256 ch, full res) + GELU ----------------
__global__ void dw3x3_gelu_kernel(const float* __restrict__ in, const float* __restrict__ w,
                                  const float* __restrict__ bias, float* __restrict__ out)
{
    int idx = blockIdx.x * 256 + threadIdx.x;          // Bc*256*HWc
    int j = idx & 255;
    int i = (idx >> 8) & 255;
    int c = (idx >> 16) & 255;
    int b = idx >> 24;
    const float* ip = in + (size_t)(b * 256 + c) * HWc;
    const float* wp = w + c * 9;
    float s = bias[c];
#pragma unroll
    for (int ky = 0; ky < 3; ky++) {
        int ii = i + ky - 1;
        if (ii < 0 || ii >= Hc) continue;
#pragma unroll
        for (int kx = 0; kx < 3; kx++) {
            int jj = j + kx - 1;
            if (jj < 0 || jj >= Wc) continue;
            s += wp[ky * 3 + kx] * ip[ii * Wc + jj];
        }
    }
    out[idx] = gelu_exact(s);
}

// ---------------- host launcher ----------------
extern "C" void kernel_launch(void* const* d_in, const int* in_sizes, int n_in,
                              void* d_out, int out_size)
{
    (void)in_sizes; (void)n_in; (void)out_size;
    const float* x1  = (const float*)d_in[0];
    const float* x2  = (const float*)d_in[1];
    const float* q1w = (const float*)d_in[2];  const float* q1b = (const float*)d_in[3];
    const float* q2w = (const float*)d_in[4];  const float* q2b = (const float*)d_in[5];
    const float* k1w = (const float*)d_in[6];  const float* k1b = (const float*)d_in[7];
    const float* k2w = (const float*)d_in[8];  const float* k2b = (const float*)d_in[9];
    const float* v1w = (const float*)d_in[10]; const float* v1b = (const float*)d_in[11];
    const float* v2w = (const float*)d_in[12]; const float* v2b = (const float*)d_in[13];
    const float* rw  = (const float*)d_in[14]; const float* rb  = (const float*)d_in[15];
    const float* m1w = (const float*)d_in[16]; const float* m1b = (const float*)d_in[17];
    const float* m2w = (const float*)d_in[18]; const float* m2b = (const float*)d_in[19];
    const float* m3w = (const float*)d_in[20]; const float* m3b = (const float*)d_in[21];
    float* out = (float*)d_out;

    float *qpre, *kpre, *vpre, *qs, *ks, *vs, *ctxp, *att, *attn, *ma, *mb;
    cudaGetSymbolAddress((void**)&qpre, g_qpre);
    cudaGetSymbolAddress((void**)&kpre, g_kpre);
    cudaGetSymbolAddress((void**)&vpre, g_vpre);
    cudaGetSymbolAddress((void**)&qs,   g_qs);
    cudaGetSymbolAddress((void**)&ks,   g_ks);
    cudaGetSymbolAddress((void**)&vs,   g_vs);
    cudaGetSymbolAddress((void**)&ctxp, g_ctx);
    cudaGetSymbolAddress((void**)&att,  g_att);
    cudaGetSymbolAddress((void**)&attn, g_attn);
    cudaGetSymbolAddress((void**)&ma,   g_ma);
    cudaGetSymbolAddress((void**)&mb,   g_mb);

    dim3 g64(HWc / 64, 1, Bc);
    // 1x1 projections with checkerboard input masks
    conv1x1_kernel<2, 0, 0><<<g64, 256>>>(x1, q1w, q1b, nullptr, qpre, 64, 64);
    conv1x1_kernel<1, 0, 0><<<g64, 256>>>(x1, k1w, k1b, nullptr, kpre, 64, 64);
    conv1x1_kernel<0, 0, 0><<<g64, 256>>>(x2, v1w, v1b, nullptr, vpre, 64, 64);
    // depthwise 3x3 + squeeze
    dw3x3_squeeze_kernel<<<(Bc*Cc*Hc*(Wc/2))/256, 256>>>(qpre, q2w, q2b, qs, 0);
    dw3x3_squeeze_kernel<<<(Bc*Cc*Hc*(Wc/2))/256, 256>>>(kpre, k2w, k2b, ks, 1);
    dw3x3_squeeze_kernel<<<(Bc*Cc*Hc*(Wc/2))/256, 256>>>(vpre, v2w, v2b, vs, 1);
    // softmaxes
    softmax_rows_kernel<<<Bc * Cc, 256>>>(ks, HWHc);
    softmax_d_kernel<<<(Bc * NH * HWHc) / 256, 256>>>(qs);
    // linear attention
    ctx_kernel<<<Bc * NH, 256>>>(ks, vs, ctxp);
    att_kernel<<<dim3(HWHc / 256, 1, Bc * NH), 256>>>(qs, ctxp, att);
    // 5x5 projection conv (parity-sparse input)
    conv5x5_kernel<<<dim3(Wc / 32, Hc, Bc), 256>>>(att, rw, rb, attn);
    // MLP
    conv1x1_kernel<0, 1, 0><<<dim3(HWc / 64, 4, Bc), 256>>>(attn, m1w, m1b, nullptr, ma, 128, 256);
    dw3x3_gelu_kernel<<<(Bc * 256 * HWc) / 256, 256>>>(ma, m2w, m2b, mb);
    conv1x1_kernel<0, 0, 1><<<dim3(HWc / 64, 2, Bc), 256>>>(mb, m3w, m3b, attn, out, 256, 128);
}

// round 6
// speedup vs baseline: 2.9747x; 2.9747x over previous
#include <cuda_runtime.h>
#include <math.h>

#define Bc   4
#define Cc   64
#define NH   4
#define Dh   16
#define Hc   256
#define Wc   256
#define HWc  (Hc*Wc)
#define HWHc (HWc/2)

// ---------------- scratch (device globals; no allocation allowed) ----------------
__device__ float g_qpre[Bc*Cc*HWc];
__device__ float g_kpre[Bc*Cc*HWc];
__device__ float g_vpre[Bc*Cc*HWc];
__device__ float g_qs  [Bc*Cc*HWHc];
__device__ float g_ks  [Bc*Cc*HWHc];
__device__ float g_vs  [Bc*Cc*HWHc];
__device__ float g_ctx [Bc*NH*Dh*Dh];
__device__ float g_ksum[Bc*Cc];
__device__ float g_kmax[Bc*Cc];
__device__ float g_att [Bc*Cc*Hc*(Wc/2)];     // squeezed att (nonanchor values)
__device__ float g_attn[Bc*2*Cc*HWc];
__device__ float g_ma  [Bc*4*Cc*HWc];
__device__ float g_mb  [Bc*4*Cc*HWc];
__device__ __align__(16) float g_w5T[64*25*128];   // [ic][tap][oc]
__device__ __align__(16) float g_m1T[128*256];     // [ic][oc]
__device__ __align__(16) float g_m3T[256*128];     // [ic][oc]

__device__ __forceinline__ float gelu_exact(float x) {
    return 0.5f * x * (1.0f + erff(x * 0.70710678118654752f));
}

// =====================================================================
// Launch 0: fused q/k/v 1x1 convs (4x4 tile, masked input) + weight transposes
// grid (2080, 3, 4), block 256.  x<1024: conv; x>=1024 (y==0,z==0): transpose.
// =====================================================================
__global__ void prep_kernel(const float* __restrict__ x1, const float* __restrict__ x2,
                            const float* __restrict__ q1w, const float* __restrict__ q1b,
                            const float* __restrict__ k1w, const float* __restrict__ k1b,
                            const float* __restrict__ v1w, const float* __restrict__ v1b,
                            const float* __restrict__ rw,  const float* __restrict__ m1w,
                            const float* __restrict__ m3w,
                            float* __restrict__ qpre, float* __restrict__ kpre,
                            float* __restrict__ vpre,
                            float* __restrict__ w5T, float* __restrict__ m1T,
                            float* __restrict__ m3T)
{
    const int tid = threadIdx.x;
    if (blockIdx.x >= 1024) {
        if (blockIdx.y != 0 || blockIdx.z != 0) return;
        int idx = (blockIdx.x - 1024) * 256 + tid;
        if (idx < 204800) {               // w5T[ic][t][oc] = rw[oc][ic][t]
            int ic = idx / 3200;
            int rem = idx - ic * 3200;
            int t = rem >> 7, oc = rem & 127;
            w5T[idx] = rw[oc * 1600 + ic * 25 + t];
        } else if (idx < 237568) {        // m1T[ic][oc] = m1w[oc][ic]
            int k = idx - 204800;
            int ic = k >> 8, oc = k & 255;
            m1T[k] = m1w[oc * 128 + ic];
        } else if (idx < 270336) {        // m3T[ic][oc] = m3w[oc][ic]
            int k = idx - 237568;
            int ic = k >> 7, oc = k & 127;
            m3T[k] = m3w[oc * 256 + ic];
        }
        return;
    }

    __shared__ __align__(16) float xs [16][64];
    __shared__ __align__(16) float wsm[16][68];
    const int which = blockIdx.y;          // 0=q (keep nonanchor), 1=k (keep anchor), 2=v
    const int b   = blockIdx.z;
    const int n0  = blockIdx.x * 64;
    const int tpx = tid & 15;
    const int toc = tid >> 4;
    const int i   = n0 >> 8;
    const int j0  = n0 & 255;

    const float* in   = (which == 2) ? x2 : x1;
    const float* w    = (which == 0) ? q1w : (which == 1) ? k1w : v1w;
    const float* bias = (which == 0) ? q1b : (which == 1) ? k1b : v1b;
    float* out        = (which == 0) ? qpre : (which == 1) ? kpre : vpre;

    float acc[4][4];
#pragma unroll
    for (int o = 0; o < 4; o++)
#pragma unroll
        for (int p = 0; p < 4; p++) acc[o][p] = 0.f;

    const float* inb = in + (size_t)b * 64 * HWc + n0;

    for (int ic0 = 0; ic0 < 64; ic0 += 16) {
#pragma unroll
        for (int l = 0; l < 4; l++) {
            int idx = tid + l * 256;
            int kk = idx >> 6, px = idx & 63;
            float v = inb[(size_t)(ic0 + kk) * HWc + px];
            int par = (i + j0 + px) & 1;
            if (which == 0 && par == 1) v = 0.f;
            if (which == 1 && par == 0) v = 0.f;
            xs[kk][px] = v;
        }
#pragma unroll
        for (int l = 0; l < 4; l++) {
            int idx = tid + l * 256;
            int kk = idx & 15, oc = idx >> 4;
            wsm[kk][oc] = w[(size_t)oc * 64 + ic0 + kk];
        }
        __syncthreads();
#pragma unroll
        for (int kk = 0; kk < 16; kk++) {
            float4 xv4 = *(const float4*)(&xs[kk][tpx << 2]);
            float4 wv4 = *(const float4*)(&wsm[kk][toc << 2]);
            float xv[4] = {xv4.x, xv4.y, xv4.z, xv4.w};
            float wv[4] = {wv4.x, wv4.y, wv4.z, wv4.w};
#pragma unroll
            for (int o = 0; o < 4; o++)
#pragma unroll
                for (int p = 0; p < 4; p++) acc[o][p] += wv[o] * xv[p];
        }
        __syncthreads();
    }
#pragma unroll
    for (int o = 0; o < 4; o++) {
        int oc = (toc << 2) + o;
        float bs = bias[oc];
        size_t obase = ((size_t)b * 64 + oc) * HWc + n0 + (tpx << 2);
#pragma unroll
        for (int p = 0; p < 4; p++) out[obase + p] = acc[o][p] + bs;
    }
}

// =====================================================================
// Launch 1: fused depthwise 3x3 + checkerboard squeeze (q/k/v) — grid (32768, 3)
// =====================================================================
__global__ void dw3x3_squeeze3_kernel(const float* __restrict__ qpre, const float* __restrict__ kpre,
                                      const float* __restrict__ vpre,
                                      const float* __restrict__ q2w, const float* __restrict__ q2b,
                                      const float* __restrict__ k2w, const float* __restrict__ k2b,
                                      const float* __restrict__ v2w, const float* __restrict__ v2b,
                                      float* __restrict__ qs, float* __restrict__ ks,
                                      float* __restrict__ vs)
{
    const int which = blockIdx.y;
    const float* in   = (which == 0) ? qpre : (which == 1) ? kpre : vpre;
    const float* w    = (which == 0) ? q2w  : (which == 1) ? k2w  : v2w;
    const float* bias = (which == 0) ? q2b  : (which == 1) ? k2b  : v2b;
    float* out        = (which == 0) ? qs   : (which == 1) ? ks   : vs;
    const int flag    = (which == 0) ? 0 : 1;

    int idx = blockIdx.x * 256 + threadIdx.x;
    int j2 = idx & 127;
    int i  = (idx >> 7) & 255;
    int c  = (idx >> 15) & 63;
    int b  = idx >> 21;
    int col = 2 * j2 + ((i + flag) & 1);
    const float* wp = w + c * 9;
    const float* ip = in + (size_t)(b * Cc + c) * HWc;
    float s = bias[c];
#pragma unroll
    for (int ky = 0; ky < 3; ky++) {
        int ii = i + ky - 1;
        if (ii < 0 || ii >= Hc) continue;
#pragma unroll
        for (int kx = 0; kx < 3; kx++) {
            int jj = col + kx - 1;
            if (jj < 0 || jj >= Wc) continue;
            s += wp[ky * 3 + kx] * ip[ii * Wc + jj];
        }
    }
    out[idx] = s;
}

// =====================================================================
// Launch 2: per-(b,c) row max of k  (+ zero ksum/ctx accumulators)
// =====================================================================
__global__ void rowmax_kernel(const float* __restrict__ ks, float* __restrict__ kmax,
                              float* __restrict__ ksum, float* __restrict__ ctxz)
{
    __shared__ float red[256];
    const int bc = blockIdx.x;
    const int tid = threadIdx.x;
    const float4* row = (const float4*)(ks + (size_t)bc * HWHc);
    float m = -1e30f;
    for (int n = tid; n < HWHc / 4; n += 256) {
        float4 v = row[n];
        m = fmaxf(m, fmaxf(fmaxf(v.x, v.y), fmaxf(v.z, v.w)));
    }
    red[tid] = m; __syncthreads();
    for (int s = 128; s > 0; s >>= 1) { if (tid < s) red[tid] = fmaxf(red[tid], red[tid + s]); __syncthreads(); }
    if (tid == 0) { kmax[bc] = red[0]; ksum[bc] = 0.f; }
    if (bc < 16) ctxz[bc * 256 + tid] = 0.f;
}

// =====================================================================
// Launch 3: ctx partial: ctxraw[bh][d][e] += sum_n exp(k-m)*v ; ksum[bh][d] += sum exp
// grid (16 chunks, 16 bh)
// =====================================================================
__global__ void ctx_partial_kernel(const float* __restrict__ ks, const float* __restrict__ vs,
                                   const float* __restrict__ kmax,
                                   float* __restrict__ ctxraw, float* __restrict__ ksum)
{
    __shared__ __align__(16) float sk[16][260];
    __shared__ __align__(16) float sv[16][260];
    __shared__ float sm[16];
    const int bh = blockIdx.y, chunk = blockIdx.x, tid = threadIdx.x;
    if (tid < 16) sm[tid] = kmax[bh * 16 + tid];
    __syncthreads();
    const float* kb = ks + (size_t)bh * Dh * HWHc + chunk * 2048;
    const float* vb = vs + (size_t)bh * Dh * HWHc + chunk * 2048;
    const int d = tid >> 4, e = tid & 15;
    float acc = 0.f, ssum = 0.f;
    for (int n0 = 0; n0 < 2048; n0 += 256) {
#pragma unroll
        for (int l = 0; l < 16; l++) {
            int idx = l * 256 + tid;
            int dd = idx >> 8, nn = idx & 255;
            sk[dd][nn] = expf(kb[(size_t)dd * HWHc + n0 + nn] - sm[dd]);
            sv[dd][nn] = vb[(size_t)dd * HWHc + n0 + nn];
        }
        __syncthreads();
#pragma unroll 8
        for (int nn = 0; nn < 256; nn += 4) {
            float4 a  = *(const float4*)&sk[d][nn];
            float4 bb = *(const float4*)&sv[e][nn];
            acc  += a.x * bb.x + a.y * bb.y + a.z * bb.z + a.w * bb.w;
            ssum += a.x + a.y + a.z + a.w;
        }
        __syncthreads();
    }
    atomicAdd(&ctxraw[bh * 256 + tid], acc);
    if (e == 0) atomicAdd(&ksum[bh * 16 + d], ssum);
}

// =====================================================================
// Launch 4: att (q softmax over d fused) -> SQUEEZED att output
// grid (128, 1, 16), block 256
// =====================================================================
__global__ void att_kernel(const float* __restrict__ q, const float* __restrict__ ctxraw,
                           const float* __restrict__ ksum, float* __restrict__ attsq)
{
    __shared__ float sctx[256];
    const int bh = blockIdx.z;
    const int tid = threadIdx.x;
    sctx[tid] = ctxraw[bh * 256 + tid] / ksum[bh * 16 + (tid >> 4)];
    __syncthreads();
    int pos = blockIdx.x * 256 + tid;
    const float* qb = q + (size_t)bh * Dh * HWHc + pos;
    float qv[16]; float m = -1e30f;
#pragma unroll
    for (int d = 0; d < 16; d++) { qv[d] = qb[(size_t)d * HWHc]; m = fmaxf(m, qv[d]); }
    float s = 0.f;
#pragma unroll
    for (int d = 0; d < 16; d++) { qv[d] = expf(qv[d] - m); s += qv[d]; }
    float inv = 1.0f / s;
#pragma unroll
    for (int d = 0; d < 16; d++) qv[d] *= inv;
    int i = pos >> 7, j2 = pos & 127;
    int b = bh >> 2, hd = bh & 3;
#pragma unroll
    for (int e = 0; e < 16; e++) {
        float o = 0.f;
#pragma unroll
        for (int d = 0; d < 16; d++) o += sctx[d * 16 + e] * qv[d];
        attsq[(((size_t)(b * Cc + hd * Dh + e) * Hc + i) << 7) + j2] = o;
    }
}

// =====================================================================
// Launch 5: 5x5 conv 64->128 as smem GEMM on squeezed (parity-sparse) input
// grid (2 parities, 256 rows, 4 b), block 256. Thread: 8 oc x 8 px.
// =====================================================================
__device__ __forceinline__ void tap5(int ic2, int ky, int kx, int aa, int pj,
                                     int tx, int ty8,
                                     const float (*xs)[5][132], const float (*ws)[25][128],
                                     float acc[8][8])
{
    int t = ky * 5 + kx;
    int jc0 = (pj + kx - 2 - aa) >> 1;           // in {-1,0,1}
    const float* xrow = &xs[ic2][ky][jc0 + 1 + tx];
    float4 w0 = *(const float4*)&ws[ic2][t][ty8];
    float4 w1 = *(const float4*)&ws[ic2][t][ty8 + 4];
    float wv[8] = {w0.x, w0.y, w0.z, w0.w, w1.x, w1.y, w1.z, w1.w};
#pragma unroll
    for (int p = 0; p < 8; p++) {
        float xv = xrow[p * 16];
#pragma unroll
        for (int o = 0; o < 8; o++) acc[o][p] = fmaf(wv[o], xv, acc[o][p]);
    }
}

__global__ __launch_bounds__(256, 2)
void conv5x5_gemm_kernel(const float* __restrict__ attsq, const float* __restrict__ w5T,
                         const float* __restrict__ bias, float* __restrict__ out)
{
    __shared__ __align__(16) float ws[2][25][128];
    __shared__ __align__(16) float xs[2][5][132];

    const int pj = blockIdx.x;       // output column parity
    const int i  = blockIdx.y;
    const int b  = blockIdx.z;
    const int tid = threadIdx.x;
    const int tx = tid & 15;
    const int ty = tid >> 4;
    const int ty8 = ty * 8;

    float acc[8][8];
#pragma unroll
    for (int o = 0; o < 8; o++)
#pragma unroll
        for (int p = 0; p < 8; p++) acc[o][p] = 0.f;

    for (int ic0 = 0; ic0 < 64; ic0 += 2) {
        __syncthreads();
        // stage weights: 2 ic x 25 taps x 128 oc, contiguous in w5T
        {
            const float4* wsrc = (const float4*)(w5T + (size_t)ic0 * 3200);
            float4* wdst = (float4*)&ws[0][0][0];
#pragma unroll
            for (int l = 0; l < 7; l++) {
                int idx = l * 256 + tid;
                if (idx < 1600) wdst[idx] = wsrc[idx];
            }
        }
        // stage squeezed input rows: 2 ic x 5 rows x 130 cols (jc in [-1,128])
#pragma unroll
        for (int l = 0; l < 6; l++) {
            int idx = l * 256 + tid;
            if (idx < 1300) {
                int ic2 = idx / 650;
                int rem = idx - ic2 * 650;
                int r = rem / 130;
                int jc = rem - r * 130 - 1;
                int ii = i + r - 2;
                float v = 0.f;
                if ((unsigned)ii < 256u && (unsigned)jc < 128u)
                    v = attsq[(((size_t)(b * Cc + ic0 + ic2) * Hc + ii) << 7) + jc];
                xs[ic2][r][jc + 1] = v;
            }
        }
        __syncthreads();

#pragma unroll
        for (int ic2 = 0; ic2 < 2; ic2++) {
#pragma unroll
            for (int ky = 0; ky < 5; ky++) {
                int aa = (i + ky) & 1;
                int kxs = (aa + pj) & 1;         // block-uniform
                if (kxs == 0) {
                    tap5(ic2, ky, 0, aa, pj, tx, ty8, xs, ws, acc);
                    tap5(ic2, ky, 2, aa, pj, tx, ty8, xs, ws, acc);
                    tap5(ic2, ky, 4, aa, pj, tx, ty8, xs, ws, acc);
                } else {
                    tap5(ic2, ky, 1, aa, pj, tx, ty8, xs, ws, acc);
                    tap5(ic2, ky, 3, aa, pj, tx, ty8, xs, ws, acc);
                }
            }
        }
    }

#pragma unroll
    for (int o = 0; o < 8; o++) {
        int oc = ty8 + o;
        float bs = bias[oc];
        float* ob = out + (((size_t)(b * 128 + oc) * Hc + i) << 8) + pj + 2 * tx;
#pragma unroll
        for (int p = 0; p < 8; p++) ob[p * 32] = acc[o][p] + bs;
    }
}

// =====================================================================
// Launches 6/8: 1x1 conv GEMM, 8x8 register tile (pre-transposed weights)
// grid (HW/128, OC/128, B), block 256
// =====================================================================
template<int ACT, int RES>
__global__ __launch_bounds__(256, 2)
void mlp1x1_kernel(const float* __restrict__ in, const float* __restrict__ wT,
                   const float* __restrict__ bias, const float* __restrict__ res,
                   float* __restrict__ out, int IC, int OC)
{
    __shared__ __align__(16) float xs[8][128];
    __shared__ __align__(16) float ws[8][128];
    const int b   = blockIdx.z;
    const int n0  = blockIdx.x * 128;
    const int oc0 = blockIdx.y * 128;
    const int tid = threadIdx.x;
    const int tx = tid & 15, ty = tid >> 4;

    float acc[8][8];
#pragma unroll
    for (int o = 0; o < 8; o++)
#pragma unroll
        for (int p = 0; p < 8; p++) acc[o][p] = 0.f;

    const float* inb = in + (size_t)b * IC * HWc + n0;
    const int kk0 = tid >> 5, px0 = (tid & 31) << 2;

    for (int ic0 = 0; ic0 < IC; ic0 += 8) {
        __syncthreads();
        *(float4*)&xs[kk0][px0] = *(const float4*)(inb + (size_t)(ic0 + kk0) * HWc + px0);
        *(float4*)&ws[kk0][px0] = *(const float4*)(wT + (size_t)(ic0 + kk0) * OC + oc0 + px0);
        __syncthreads();
#pragma unroll
        for (int kk = 0; kk < 8; kk++) {
            float4 x0 = *(const float4*)&xs[kk][tx * 8];
            float4 x1 = *(const float4*)&xs[kk][tx * 8 + 4];
            float4 w0 = *(const float4*)&ws[kk][ty * 8];
            float4 w1 = *(const float4*)&ws[kk][ty * 8 + 4];
            float xv[8] = {x0.x, x0.y, x0.z, x0.w, x1.x, x1.y, x1.z, x1.w};
            float wv[8] = {w0.x, w0.y, w0.z, w0.w, w1.x, w1.y, w1.z, w1.w};
#pragma unroll
            for (int o = 0; o < 8; o++)
#pragma unroll
                for (int p = 0; p < 8; p++) acc[o][p] = fmaf(wv[o], xv[p], acc[o][p]);
        }
    }

#pragma unroll
    for (int o = 0; o < 8; o++) {
        int oc = oc0 + ty * 8 + o;
        float bs = bias[oc];
        size_t ob = ((size_t)b * OC + oc) * HWc + n0 + tx * 8;
#pragma unroll
        for (int p = 0; p < 8; p++) {
            float v = acc[o][p] + bs;
            if (ACT) v = gelu_exact(v);
            if (RES) v += res[ob + p];
            out[ob + p] = v;
        }
    }
}

// =====================================================================
// Launch 7: depthwise 3x3 (256 ch) + GELU, 4 px/thread
// =====================================================================
__global__ void dw3x3_gelu_kernel(const float* __restrict__ in, const float* __restrict__ w,
                                  const float* __restrict__ bias, float* __restrict__ out)
{
    int idx = blockIdx.x * 256 + threadIdx.x;      // Bc*256*Hc*64
    int j4 = (idx & 63) << 2;
    int i  = (idx >> 6) & 255;
    int c  = (idx >> 14) & 255;
    int b  = idx >> 22;
    const float* ip = in + (size_t)(b * 256 + c) * HWc;
    const float* wp = w + c * 9;
    float bs = bias[c];
    float s0 = bs, s1 = bs, s2 = bs, s3 = bs;
#pragma unroll
    for (int ky = 0; ky < 3; ky++) {
        int ii = i + ky - 1;
        if (ii < 0 || ii >= Hc) continue;
        const float* row = ip + ii * Wc;
        float r[6];
        r[0] = (j4 > 0) ? row[j4 - 1] : 0.f;
        float4 mm = *(const float4*)(row + j4);
        r[1] = mm.x; r[2] = mm.y; r[3] = mm.z; r[4] = mm.w;
        r[5] = (j4 + 4 < Wc) ? row[j4 + 4] : 0.f;
#pragma unroll
        for (int kx = 0; kx < 3; kx++) {
            float wv = wp[ky * 3 + kx];
            s0 += wv * r[kx];     s1 += wv * r[kx + 1];
            s2 += wv * r[kx + 2]; s3 += wv * r[kx + 3];
        }
    }
    float4 o;
    o.x = gelu_exact(s0); o.y = gelu_exact(s1);
    o.z = gelu_exact(s2); o.w = gelu_exact(s3);
    *(float4*)(out + (size_t)idx * 4) = o;
}

// ---------------- host launcher ----------------
extern "C" void kernel_launch(void* const* d_in, const int* in_sizes, int n_in,
                              void* d_out, int out_size)
{
    (void)in_sizes; (void)n_in; (void)out_size;
    const float* x1  = (const float*)d_in[0];
    const float* x2  = (const float*)d_in[1];
    const float* q1w = (const float*)d_in[2];  const float* q1b = (const float*)d_in[3];
    const float* q2w = (const float*)d_in[4];  const float* q2b = (const float*)d_in[5];
    const float* k1w = (const float*)d_in[6];  const float* k1b = (const float*)d_in[7];
    const float* k2w = (const float*)d_in[8];  const float* k2b = (const float*)d_in[9];
    const float* v1w = (const float*)d_in[10]; const float* v1b = (const float*)d_in[11];
    const float* v2w = (const float*)d_in[12]; const float* v2b = (const float*)d_in[13];
    const float* rw  = (const float*)d_in[14]; const float* rb  = (const float*)d_in[15];
    const float* m1w = (const float*)d_in[16]; const float* m1b = (const float*)d_in[17];
    const float* m2w = (const float*)d_in[18]; const float* m2b = (const float*)d_in[19];
    const float* m3w = (const float*)d_in[20]; const float* m3b = (const float*)d_in[21];
    float* out = (float*)d_out;

    float *qpre, *kpre, *vpre, *qs, *ks, *vs, *ctxp, *ksum, *kmax, *att, *attn, *ma, *mb;
    float *w5T, *m1T, *m3T;
    cudaGetSymbolAddress((void**)&qpre, g_qpre);
    cudaGetSymbolAddress((void**)&kpre, g_kpre);
    cudaGetSymbolAddress((void**)&vpre, g_vpre);
    cudaGetSymbolAddress((void**)&qs,   g_qs);
    cudaGetSymbolAddress((void**)&ks,   g_ks);
    cudaGetSymbolAddress((void**)&vs,   g_vs);
    cudaGetSymbolAddress((void**)&ctxp, g_ctx);
    cudaGetSymbolAddress((void**)&ksum, g_ksum);
    cudaGetSymbolAddress((void**)&kmax, g_kmax);
    cudaGetSymbolAddress((void**)&att,  g_att);
    cudaGetSymbolAddress((void**)&attn, g_attn);
    cudaGetSymbolAddress((void**)&ma,   g_ma);
    cudaGetSymbolAddress((void**)&mb,   g_mb);
    cudaGetSymbolAddress((void**)&w5T,  g_w5T);
    cudaGetSymbolAddress((void**)&m1T,  g_m1T);
    cudaGetSymbolAddress((void**)&m3T,  g_m3T);

    // 0: qkv 1x1 + weight transposes
    prep_kernel<<<dim3(2080, 3, Bc), 256>>>(x1, x2, q1w, q1b, k1w, k1b, v1w, v1b,
                                            rw, m1w, m3w, qpre, kpre, vpre, w5T, m1T, m3T);
    // 1: depthwise 3x3 + squeeze (q/k/v)
    dw3x3_squeeze3_kernel<<<dim3((Bc*Cc*Hc*(Wc/2))/256, 3), 256>>>(
        qpre, kpre, vpre, q2w, q2b, k2w, k2b, v2w, v2b, qs, ks, vs);
    // 2: k row-max (+ zero accumulators)
    rowmax_kernel<<<Bc * Cc, 256>>>(ks, kmax, ksum, ctxp);
    // 3: ctx partial accumulation (k softmax fused, atomic)
    ctx_partial_kernel<<<dim3(16, Bc * NH), 256>>>(ks, vs, kmax, ctxp, ksum);
    // 4: att (q softmax fused) -> squeezed att
    att_kernel<<<dim3(HWHc / 256, 1, Bc * NH), 256>>>(qs, ctxp, ksum, att);
    // 5: 5x5 conv (GEMM on parity-sparse input)  [profiled by ncu -s 5 -c 1]
    conv5x5_gemm_kernel<<<dim3(2, Hc, Bc), 256>>>(att, w5T, rb, attn);
    // 6: MLP expand + GELU
    mlp1x1_kernel<1, 0><<<dim3(HWc / 128, 2, Bc), 256>>>(attn, m1T, m1b, nullptr, ma, 128, 256);
    // 7: depthwise 3x3 + GELU
    dw3x3_gelu_kernel<<<(Bc * 256 * HWc / 4) / 256, 256>>>(ma, m2w, m2b, mb);
    // 8: MLP contract + residual
    mlp1x1_kernel<0, 1><<<dim3(HWc / 128, 1, Bc), 256>>>(mb, m3T, m3b, attn, out, 256, 128);
}